// round 4
// baseline (speedup 1.0000x reference)
#include <cuda_runtime.h>
#include <cuda_bf16.h>
#include <cstdint>

#define NN   50000
#define NE   800000
#define FIN  128
#define HID  256
#define NG   128

// ---------------- device scratch (static allocation is allowed) -------------
__device__ float4 g_ax[NN * FIN / 4];   // spmm(x)            [N,128]
__device__ float4 g_h1[NN * HID / 4];   // relu(ax@W1+b1)     [N,256]
__device__ float4 g_t2[NN * HID / 4];   // h1@W2              [N,256]
__device__ float4 g_h2[NN * HID / 4];   // relu(spmm(t2)+b2)  [N,256]
__device__ int    g_deg[NN];
__device__ int    g_rp[NN + 1];
__device__ int    g_cursor[NN];
__device__ int    g_srcs[NE];
__device__ float  g_ws[NE];
__device__ float  g_pool[NG * HID];

// ---------------- CSR build -------------------------------------------------
__global__ void zero_kernel() {
    int i = blockIdx.x * blockDim.x + threadIdx.x;
    if (i < NN) g_deg[i] = 0;
    if (i < NG * HID) g_pool[i] = 0.0f;
}

__global__ void hist_kernel(const int* __restrict__ dst) {
    int e = blockIdx.x * blockDim.x + threadIdx.x;
    if (e < NE) atomicAdd(&g_deg[dst[e]], 1);
}

// single-block exclusive scan of g_deg -> g_rp (and g_cursor copy)
__global__ void scan_kernel() {
    __shared__ int warp_sums[32];
    __shared__ int s_carry;
    if (threadIdx.x == 0) s_carry = 0;
    __syncthreads();
    int lane = threadIdx.x & 31, w = threadIdx.x >> 5;
    for (int base = 0; base < NN; base += blockDim.x) {
        int idx = base + threadIdx.x;
        int v = (idx < NN) ? g_deg[idx] : 0;
        int incl = v;
        #pragma unroll
        for (int o = 1; o < 32; o <<= 1) {
            int t = __shfl_up_sync(0xffffffffu, incl, o);
            if (lane >= o) incl += t;
        }
        if (lane == 31) warp_sums[w] = incl;
        __syncthreads();
        if (w == 0) {
            int s = warp_sums[lane];
            #pragma unroll
            for (int o = 1; o < 32; o <<= 1) {
                int t = __shfl_up_sync(0xffffffffu, s, o);
                if (lane >= o) s += t;
            }
            warp_sums[lane] = s;
        }
        __syncthreads();
        int warp_off = (w > 0) ? warp_sums[w - 1] : 0;
        int excl = s_carry + warp_off + incl - v;
        if (idx < NN) { g_rp[idx] = excl; g_cursor[idx] = excl; }
        __syncthreads();
        if (threadIdx.x == blockDim.x - 1) s_carry = s_carry + warp_off + incl;
        __syncthreads();
    }
    if (threadIdx.x == 0) g_rp[NN] = s_carry;
}

__global__ void fill_kernel(const int* __restrict__ src, const int* __restrict__ dst,
                            const float* __restrict__ ew) {
    int e = blockIdx.x * blockDim.x + threadIdx.x;
    if (e < NE) {
        int p = atomicAdd(&g_cursor[dst[e]], 1);
        g_srcs[p] = src[e];
        g_ws[p]   = ew[e];
    }
}

// ---------------- SPMM (warp per dst node, gather-reduce) -------------------
__global__ void __launch_bounds__(256) spmm128_kernel(const float4* __restrict__ x4) {
    int warp = (blockIdx.x * blockDim.x + threadIdx.x) >> 5;
    int lane = threadIdx.x & 31;
    if (warp >= NN) return;
    int e0 = g_rp[warp], e1 = g_rp[warp + 1];
    float4 acc = make_float4(0.f, 0.f, 0.f, 0.f);
    for (int e = e0; e < e1; e++) {
        int   s = g_srcs[e];
        float w = g_ws[e];
        float4 v = __ldg(&x4[s * (FIN / 4) + lane]);
        acc.x += w * v.x; acc.y += w * v.y; acc.z += w * v.z; acc.w += w * v.w;
    }
    g_ax[warp * (FIN / 4) + lane] = acc;
}

__global__ void __launch_bounds__(256) spmm256_kernel(const float* __restrict__ b2) {
    int warp = (blockIdx.x * blockDim.x + threadIdx.x) >> 5;
    int lane = threadIdx.x & 31;
    if (warp >= NN) return;
    int e0 = g_rp[warp], e1 = g_rp[warp + 1];
    float4 a0 = make_float4(0.f, 0.f, 0.f, 0.f);
    float4 a1 = make_float4(0.f, 0.f, 0.f, 0.f);
    for (int e = e0; e < e1; e++) {
        int   s = g_srcs[e];
        float w = g_ws[e];
        const float4* row = &g_t2[s * (HID / 4)];
        float4 v0 = __ldg(&row[lane]);
        float4 v1 = __ldg(&row[lane + 32]);
        a0.x += w * v0.x; a0.y += w * v0.y; a0.z += w * v0.z; a0.w += w * v0.w;
        a1.x += w * v1.x; a1.y += w * v1.y; a1.z += w * v1.z; a1.w += w * v1.w;
    }
    const float4* b4 = (const float4*)b2;
    float4 c0 = __ldg(&b4[lane]);
    float4 c1 = __ldg(&b4[lane + 32]);
    a0.x = fmaxf(a0.x + c0.x, 0.f); a0.y = fmaxf(a0.y + c0.y, 0.f);
    a0.z = fmaxf(a0.z + c0.z, 0.f); a0.w = fmaxf(a0.w + c0.w, 0.f);
    a1.x = fmaxf(a1.x + c1.x, 0.f); a1.y = fmaxf(a1.y + c1.y, 0.f);
    a1.z = fmaxf(a1.z + c1.z, 0.f); a1.w = fmaxf(a1.w + c1.w, 0.f);
    g_h2[warp * (HID / 4) + lane]      = a0;
    g_h2[warp * (HID / 4) + lane + 32] = a1;
}

// ---------------- split-bf16 tensor-core GEMM -------------------------------
// C = A[M,K] @ W[K,N] (+bias, relu), fp32-accurate via 3-term bf16 split:
//   A = Ah + Al (Ah=bf16_rn(A), Al=bf16_rn(A-Ah)), same for W.
//   C = Ah*Bh + Al*Bh + Ah*Bl   (dropped Al*Bl ~ 2^-18)
// Block tile 128x128, K-tile 32. 8 warps, each 32(m) x 64(n), mma.m16n8k16.
// Smem stride 136 words: fragment LDS bank = 8*tg+gid -> bijective, no conflicts.
#define GBM 128
#define GBN 128
#define GBK 32
#define SS  136

__device__ __forceinline__ uint32_t pack2(__nv_bfloat16 lo, __nv_bfloat16 hi) {
    __nv_bfloat162 t = __halves2bfloat162(lo, hi);  // .x in low 16 bits
    return *(uint32_t*)&t;
}
__device__ __forceinline__ void split2(float a, float b, uint32_t& h, uint32_t& l) {
    __nv_bfloat16 ah = __float2bfloat16_rn(a);
    __nv_bfloat16 bh = __float2bfloat16_rn(b);
    __nv_bfloat16 al = __float2bfloat16_rn(a - __bfloat162float(ah));
    __nv_bfloat16 bl = __float2bfloat16_rn(b - __bfloat162float(bh));
    h = pack2(ah, bh);
    l = pack2(al, bl);
}

#define MMA_BF16(C, A0, A1, A2, A3, B0, B1)                                    \
    asm volatile(                                                              \
        "mma.sync.aligned.m16n8k16.row.col.f32.bf16.bf16.f32 "                 \
        "{%0,%1,%2,%3}, {%4,%5,%6,%7}, {%8,%9}, {%0,%1,%2,%3};"                \
        : "+f"(C[0]), "+f"(C[1]), "+f"(C[2]), "+f"(C[3])                       \
        : "r"(A0), "r"(A1), "r"(A2), "r"(A3), "r"(B0), "r"(B1))

__global__ void __launch_bounds__(256) gemm_bf16x2_kernel(
    const float* __restrict__ A, const float* __restrict__ W,
    const float* __restrict__ bias, float* __restrict__ C,
    int M, int N, int K, int doBiasRelu)
{
    // [k/2][m or n] packed bf16x2 along k
    __shared__ uint32_t As_h[GBK / 2][SS];
    __shared__ uint32_t As_l[GBK / 2][SS];
    __shared__ uint32_t Bs_h[GBK / 2][SS];
    __shared__ uint32_t Bs_l[GBK / 2][SS];

    int tid  = threadIdx.x;
    int lane = tid & 31;
    int warp = tid >> 5;              // 0..7
    int warp_m = warp & 3;            // row base 32*warp_m
    int warp_n = warp >> 2;           // col base 64*warp_n
    int gid = lane >> 2;              // 0..7
    int tg  = lane & 3;               // 0..3

    int bm0 = blockIdx.x * GBM;
    int bn0 = blockIdx.y * GBN;

    float c[2][8][4];
    #pragma unroll
    for (int mt = 0; mt < 2; mt++)
        #pragma unroll
        for (int nt = 0; nt < 8; nt++)
            #pragma unroll
            for (int r = 0; r < 4; r++) c[mt][nt][r] = 0.f;

    for (int k0 = 0; k0 < K; k0 += GBK) {
        // ---- A tile: 128 rows x 32 k-cols = 1024 float4, 4 per thread ----
        #pragma unroll
        for (int i = 0; i < 4; i++) {
            int idx = tid + i * 256;
            int r = idx >> 3, c4 = idx & 7;     // r: 0..127, c4: 0..7 (float4 along k)
            float4 v = make_float4(0.f, 0.f, 0.f, 0.f);
            if (bm0 + r < M)
                v = *(const float4*)&A[(size_t)(bm0 + r) * K + k0 + c4 * 4];
            uint32_t h0, l0, h1, l1;
            split2(v.x, v.y, h0, l0);
            split2(v.z, v.w, h1, l1);
            As_h[c4 * 2][r]     = h0;  As_l[c4 * 2][r]     = l0;
            As_h[c4 * 2 + 1][r] = h1;  As_l[c4 * 2 + 1][r] = l1;
        }
        // ---- B tile: 32 k-rows x 128 n-cols; pack pairs of k-rows ----
        #pragma unroll
        for (int i = 0; i < 2; i++) {
            int idx = tid + i * 256;
            int j = idx >> 5, c4 = idx & 31;    // j: 0..15 (k-pair), c4: n-group
            const float* r0 = &W[(size_t)(k0 + 2 * j) * N + bn0 + c4 * 4];
            float4 v0 = *(const float4*)r0;          // k = 2j
            float4 v1 = *(const float4*)(r0 + N);    // k = 2j+1
            uint32_t h, l;
            split2(v0.x, v1.x, h, l); Bs_h[j][c4 * 4 + 0] = h; Bs_l[j][c4 * 4 + 0] = l;
            split2(v0.y, v1.y, h, l); Bs_h[j][c4 * 4 + 1] = h; Bs_l[j][c4 * 4 + 1] = l;
            split2(v0.z, v1.z, h, l); Bs_h[j][c4 * 4 + 2] = h; Bs_l[j][c4 * 4 + 2] = l;
            split2(v0.w, v1.w, h, l); Bs_h[j][c4 * 4 + 3] = h; Bs_l[j][c4 * 4 + 3] = l;
        }
        __syncthreads();

        #pragma unroll
        for (int ks = 0; ks < GBK / 16; ks++) {
            int jb = ks * 8;
            uint32_t ah[2][4], al[2][4];
            #pragma unroll
            for (int mt = 0; mt < 2; mt++) {
                int mr = warp_m * 32 + mt * 16;
                ah[mt][0] = As_h[jb + tg    ][mr + gid    ];
                ah[mt][1] = As_h[jb + tg    ][mr + gid + 8];
                ah[mt][2] = As_h[jb + tg + 4][mr + gid    ];
                ah[mt][3] = As_h[jb + tg + 4][mr + gid + 8];
                al[mt][0] = As_l[jb + tg    ][mr + gid    ];
                al[mt][1] = As_l[jb + tg    ][mr + gid + 8];
                al[mt][2] = As_l[jb + tg + 4][mr + gid    ];
                al[mt][3] = As_l[jb + tg + 4][mr + gid + 8];
            }
            #pragma unroll
            for (int nt = 0; nt < 8; nt++) {
                int nc = warp_n * 64 + nt * 8 + gid;
                uint32_t bh0 = Bs_h[jb + tg    ][nc];
                uint32_t bh1 = Bs_h[jb + tg + 4][nc];
                uint32_t bl0 = Bs_l[jb + tg    ][nc];
                uint32_t bl1 = Bs_l[jb + tg + 4][nc];
                #pragma unroll
                for (int mt = 0; mt < 2; mt++) {
                    MMA_BF16(c[mt][nt], ah[mt][0], ah[mt][1], ah[mt][2], ah[mt][3], bh0, bh1);
                    MMA_BF16(c[mt][nt], al[mt][0], al[mt][1], al[mt][2], al[mt][3], bh0, bh1);
                    MMA_BF16(c[mt][nt], ah[mt][0], ah[mt][1], ah[mt][2], ah[mt][3], bl0, bl1);
                }
            }
        }
        __syncthreads();
    }

    // epilogue: c0/c1 at (row=gid, col=2tg,2tg+1), c2/c3 at row=gid+8
    #pragma unroll
    for (int mt = 0; mt < 2; mt++) {
        int rbase = bm0 + warp_m * 32 + mt * 16 + gid;
        #pragma unroll
        for (int nt = 0; nt < 8; nt++) {
            int col = bn0 + warp_n * 64 + nt * 8 + 2 * tg;
            float v0 = c[mt][nt][0], v1 = c[mt][nt][1];
            float v2 = c[mt][nt][2], v3 = c[mt][nt][3];
            if (doBiasRelu) {
                float bb0 = bias[col], bb1 = bias[col + 1];
                v0 = fmaxf(v0 + bb0, 0.f); v1 = fmaxf(v1 + bb1, 0.f);
                v2 = fmaxf(v2 + bb0, 0.f); v3 = fmaxf(v3 + bb1, 0.f);
            }
            if (rbase < M)     *(float2*)&C[(size_t)rbase * N + col]       = make_float2(v0, v1);
            if (rbase + 8 < M) *(float2*)&C[(size_t)(rbase + 8) * N + col] = make_float2(v2, v3);
        }
    }
}

// ---------------- pooling (seg_ids sorted) ----------------------------------
#define POOL_ROWS 512
__global__ void __launch_bounds__(256) pool_kernel(const int* __restrict__ seg) {
    __shared__ int segs[POOL_ROWS];
    int r0 = blockIdx.x * POOL_ROWS;
    int nr = min(POOL_ROWS, NN - r0);
    if (nr <= 0) return;
    for (int r = threadIdx.x; r < nr; r += blockDim.x) segs[r] = seg[r0 + r];
    __syncthreads();
    int col = threadIdx.x;  // 256 cols
    const float* h2 = (const float*)g_h2;
    float acc = 0.f;
    int cur = segs[0];
    for (int r = 0; r < nr; r++) {
        int s = segs[r];
        if (s != cur) { atomicAdd(&g_pool[cur * HID + col], acc); acc = 0.f; cur = s; }
        acc += h2[(size_t)(r0 + r) * HID + col];
    }
    atomicAdd(&g_pool[cur * HID + col], acc);
}

// ---------------- head: out = relu(g@Wd+bd) @ Wo + bo -----------------------
__global__ void __launch_bounds__(256) head_kernel(
    const float* __restrict__ Wd, const float* __restrict__ bd,
    const float* __restrict__ Wo, const float* __restrict__ bo,
    float* __restrict__ out)
{
    __shared__ float grow[HID];
    __shared__ float red[HID];
    int i = blockIdx.x, t = threadIdx.x;
    grow[t] = g_pool[i * HID + t];
    __syncthreads();
    float acc = bd[t];
    #pragma unroll 8
    for (int k = 0; k < HID; k++) acc += grow[k] * Wd[k * HID + t];
    acc = fmaxf(acc, 0.f);
    red[t] = acc * Wo[t];
    __syncthreads();
    for (int s = 128; s > 0; s >>= 1) {
        if (t < s) red[t] += red[t + s];
        __syncthreads();
    }
    if (t == 0) out[i] = red[0] + bo[0];
}

// ---------------- launch ----------------------------------------------------
extern "C" void kernel_launch(void* const* d_in, const int* in_sizes, int n_in,
                              void* d_out, int out_size)
{
    const float* x   = (const float*)d_in[0];
    const int*   esr = (const int*)  d_in[1];
    const int*   eds = (const int*)  d_in[2];
    const float* ew  = (const float*)d_in[3];
    const int*   seg = (const int*)  d_in[4];
    const float* W1  = (const float*)d_in[5];
    const float* b1  = (const float*)d_in[6];
    const float* W2  = (const float*)d_in[7];
    const float* b2  = (const float*)d_in[8];
    const float* Wd  = (const float*)d_in[9];
    const float* bd  = (const float*)d_in[10];
    const float* Wo  = (const float*)d_in[11];
    const float* bo  = (const float*)d_in[12];
    float* out = (float*)d_out;

    void *p_ax, *p_h1, *p_t2;
    cudaGetSymbolAddress(&p_ax, g_ax);
    cudaGetSymbolAddress(&p_h1, g_h1);
    cudaGetSymbolAddress(&p_t2, g_t2);

    // 1) zero counters + pool accumulator
    zero_kernel<<<(NN + 255) / 256, 256>>>();
    // 2) CSR build
    hist_kernel<<<(NE + 255) / 256, 256>>>(eds);
    scan_kernel<<<1, 1024>>>();
    fill_kernel<<<(NE + 255) / 256, 256>>>(esr, eds, ew);
    // 3) spmm(x) -> ax  [N,128]
    spmm128_kernel<<<NN / 8, 256>>>((const float4*)x);
    // 4) h1 = relu(ax @ W1 + b1)
    {
        dim3 grid((NN + GBM - 1) / GBM, HID / GBN);
        gemm_bf16x2_kernel<<<grid, 256>>>((const float*)p_ax, W1, b1, (float*)p_h1,
                                          NN, HID, FIN, 1);
    }
    // 5) t2 = h1 @ W2
    {
        dim3 grid((NN + GBM - 1) / GBM, HID / GBN);
        gemm_bf16x2_kernel<<<grid, 256>>>((const float*)p_h1, W2, b1 /*unused*/, (float*)p_t2,
                                          NN, HID, HID, 0);
    }
    // 6) h2 = relu(spmm(t2) + b2)
    spmm256_kernel<<<NN / 8, 256>>>(b2);
    // 7) pool
    pool_kernel<<<(NN + POOL_ROWS - 1) / POOL_ROWS, 256>>>(seg);
    // 8) head
    head_kernel<<<NG, HID>>>(Wd, bd, Wo, bo, out);
}

// round 7
// speedup vs baseline: 1.1110x; 1.1110x over previous
#include <cuda_runtime.h>
#include <cuda_bf16.h>
#include <cstdint>

#define NN   50000
#define NE   800000
#define FIN  128
#define HID  256
#define NG   128
#define NBLK 196   // ceil(NN/256)

// ---------------- device scratch (static allocation is allowed) -------------
__device__ float4 g_ax[NN * FIN / 4];   // spmm(x)            [N,128]
__device__ float4 g_h1[NN * HID / 4];   // relu(ax@W1+b1)     [N,256]
__device__ float4 g_t2[NN * HID / 4];   // h1@W2              [N,256]
__device__ float4 g_h2[NN * HID / 4];   // relu(spmm(t2)+b2)  [N,256]
__device__ int    g_deg[NN];
__device__ int    g_rp[NN + 1];
__device__ int    g_cursor[NN];
__device__ int    g_srcs[NE];
__device__ float  g_ws[NE];
__device__ float  g_pool[NG * HID];
__device__ int    g_bsum[256];
__device__ int    g_bpre[256];
__device__ float  g_W1t[HID * FIN];     // W1^T  [256][128]
__device__ float  g_W2t[HID * HID];     // W2^T  [256][256]

// ---------------- CSR build -------------------------------------------------
__global__ void zero_kernel() {
    int i = blockIdx.x * blockDim.x + threadIdx.x;
    if (i < NN) g_deg[i] = 0;
    if (i < NG * HID) g_pool[i] = 0.0f;
}

__global__ void hist_kernel(const int* __restrict__ dst) {
    int e = blockIdx.x * blockDim.x + threadIdx.x;
    if (e < NE) atomicAdd(&g_deg[dst[e]], 1);
}

// block-level sums of g_deg
__global__ void __launch_bounds__(256) scan_pre_kernel() {
    __shared__ int s[256];
    int i = blockIdx.x * 256 + threadIdx.x;
    int v = (i < NN) ? g_deg[i] : 0;
    s[threadIdx.x] = v;
    __syncthreads();
    for (int off = 128; off > 0; off >>= 1) {
        if (threadIdx.x < off) s[threadIdx.x] += s[threadIdx.x + off];
        __syncthreads();
    }
    if (threadIdx.x == 0) g_bsum[blockIdx.x] = s[0];
}

// single small block: exclusive scan of the 196 block sums
__global__ void __launch_bounds__(256) scan_mid_kernel() {
    __shared__ int s[256];
    int t = threadIdx.x;
    int v = (t < NBLK) ? g_bsum[t] : 0;
    s[t] = v;
    __syncthreads();
    for (int off = 1; off < 256; off <<= 1) {
        int add = (t >= off) ? s[t - off] : 0;
        __syncthreads();
        s[t] += add;
        __syncthreads();
    }
    g_bpre[t] = s[t] - v;           // exclusive prefix
    if (t == 255) g_rp[NN] = s[255];
}

// per-block exclusive scan + global offset -> g_rp, g_cursor
__global__ void __launch_bounds__(256) scan_post_kernel() {
    __shared__ int wsum[8];
    int t = threadIdx.x, lane = t & 31, w = t >> 5;
    int i = blockIdx.x * 256 + t;
    int v = (i < NN) ? g_deg[i] : 0;
    int incl = v;
    #pragma unroll
    for (int o = 1; o < 32; o <<= 1) {
        int x = __shfl_up_sync(0xffffffffu, incl, o);
        if (lane >= o) incl += x;
    }
    if (lane == 31) wsum[w] = incl;
    __syncthreads();
    if (w == 0 && lane < 8) {
        int x = wsum[lane];
        #pragma unroll
        for (int o = 1; o < 8; o <<= 1) {
            int y = __shfl_up_sync(0xffu, x, o);
            if (lane >= o) x += y;
        }
        wsum[lane] = x;
    }
    __syncthreads();
    int base = g_bpre[blockIdx.x] + ((w > 0) ? wsum[w - 1] : 0);
    int excl = base + incl - v;
    if (i < NN) { g_rp[i] = excl; g_cursor[i] = excl; }
}

__global__ void fill_kernel(const int* __restrict__ src, const int* __restrict__ dst,
                            const float* __restrict__ ew) {
    int e = blockIdx.x * blockDim.x + threadIdx.x;
    if (e < NE) {
        int p = atomicAdd(&g_cursor[dst[e]], 1);
        g_srcs[p] = src[e];
        g_ws[p]   = ew[e];
    }
}

// ---------------- weight transpose: dst[n*K+k] = src[k*N+n] -----------------
__global__ void __launch_bounds__(256) transpose_kernel(
    const float* __restrict__ src, float* __restrict__ dst, int K, int N)
{
    __shared__ float tile[32][33];
    int kb = blockIdx.x * 32, nb = blockIdx.y * 32;
    int tx = threadIdx.x & 31, ty = threadIdx.x >> 5;   // 32 x 8
    #pragma unroll
    for (int j = 0; j < 4; j++)
        tile[ty + 8 * j][tx] = src[(size_t)(kb + ty + 8 * j) * N + nb + tx];
    __syncthreads();
    #pragma unroll
    for (int j = 0; j < 4; j++)
        dst[(size_t)(nb + ty + 8 * j) * K + kb + tx] = tile[tx][ty + 8 * j];
}

// ---------------- SPMM (warp per dst node, gather-reduce) -------------------
__global__ void __launch_bounds__(256) spmm128_kernel(const float4* __restrict__ x4) {
    int warp = (blockIdx.x * blockDim.x + threadIdx.x) >> 5;
    int lane = threadIdx.x & 31;
    if (warp >= NN) return;
    int e0 = g_rp[warp], e1 = g_rp[warp + 1];
    float4 acc = make_float4(0.f, 0.f, 0.f, 0.f);
    for (int e = e0; e < e1; e++) {
        int   s = g_srcs[e];
        float w = g_ws[e];
        float4 v = __ldg(&x4[s * (FIN / 4) + lane]);
        acc.x += w * v.x; acc.y += w * v.y; acc.z += w * v.z; acc.w += w * v.w;
    }
    g_ax[warp * (FIN / 4) + lane] = acc;
}

__global__ void __launch_bounds__(256) spmm256_kernel(const float* __restrict__ b2) {
    int warp = (blockIdx.x * blockDim.x + threadIdx.x) >> 5;
    int lane = threadIdx.x & 31;
    if (warp >= NN) return;
    int e0 = g_rp[warp], e1 = g_rp[warp + 1];
    float4 a0 = make_float4(0.f, 0.f, 0.f, 0.f);
    float4 a1 = make_float4(0.f, 0.f, 0.f, 0.f);
    for (int e = e0; e < e1; e++) {
        int   s = g_srcs[e];
        float w = g_ws[e];
        const float4* row = &g_t2[s * (HID / 4)];
        float4 v0 = __ldg(&row[lane]);
        float4 v1 = __ldg(&row[lane + 32]);
        a0.x += w * v0.x; a0.y += w * v0.y; a0.z += w * v0.z; a0.w += w * v0.w;
        a1.x += w * v1.x; a1.y += w * v1.y; a1.z += w * v1.z; a1.w += w * v1.w;
    }
    const float4* b4 = (const float4*)b2;
    float4 c0 = __ldg(&b4[lane]);
    float4 c1 = __ldg(&b4[lane + 32]);
    a0.x = fmaxf(a0.x + c0.x, 0.f); a0.y = fmaxf(a0.y + c0.y, 0.f);
    a0.z = fmaxf(a0.z + c0.z, 0.f); a0.w = fmaxf(a0.w + c0.w, 0.f);
    a1.x = fmaxf(a1.x + c1.x, 0.f); a1.y = fmaxf(a1.y + c1.y, 0.f);
    a1.z = fmaxf(a1.z + c1.z, 0.f); a1.w = fmaxf(a1.w + c1.w, 0.f);
    g_h2[warp * (HID / 4) + lane]      = a0;
    g_h2[warp * (HID / 4) + lane + 32] = a1;
}

// ---------------- split-bf16 tensor-core GEMM with ldmatrix -----------------
// C = A[M,K] @ W[K,N] (+bias, relu); B supplied pre-transposed Bt[N,K].
// 3-term bf16 split: C = Ah*Bh + Al*Bh + Ah*Bl (drop Al*Bl ~ 2^-18).
// smem tiles [row][k] bf16, row pitch 40 halfwords (80B): ldmatrix phase
// chunk index = 5*row mod 8 -> bijective -> conflict-free LDSM.
#define GBM 128
#define GBN 128
#define GBK 32
#define APITCH 40

__device__ __forceinline__ uint32_t pack2(__nv_bfloat16 lo, __nv_bfloat16 hi) {
    __nv_bfloat162 t = __halves2bfloat162(lo, hi);  // .x -> low 16 bits
    return *(uint32_t*)&t;
}
__device__ __forceinline__ void split2(float a, float b, uint32_t& h, uint32_t& l) {
    __nv_bfloat16 ah = __float2bfloat16_rn(a);
    __nv_bfloat16 bh = __float2bfloat16_rn(b);
    __nv_bfloat16 al = __float2bfloat16_rn(a - __bfloat162float(ah));
    __nv_bfloat16 bl = __float2bfloat16_rn(b - __bfloat162float(bh));
    h = pack2(ah, bh);
    l = pack2(al, bl);
}

#define LDSM4(R, addr)                                                         \
    asm volatile("ldmatrix.sync.aligned.m8n8.x4.shared.b16 {%0,%1,%2,%3}, [%4];" \
        : "=r"(R[0]), "=r"(R[1]), "=r"(R[2]), "=r"(R[3]) : "r"(addr))

#define MMA_BF16(C, A, B0, B1)                                                 \
    asm volatile(                                                              \
        "mma.sync.aligned.m16n8k16.row.col.f32.bf16.bf16.f32 "                 \
        "{%0,%1,%2,%3}, {%4,%5,%6,%7}, {%8,%9}, {%0,%1,%2,%3};"                \
        : "+f"(C[0]), "+f"(C[1]), "+f"(C[2]), "+f"(C[3])                       \
        : "r"(A[0]), "r"(A[1]), "r"(A[2]), "r"(A[3]), "r"(B0), "r"(B1))

__global__ void __launch_bounds__(256, 2) gemm_bf16_ldsm_kernel(
    const float* __restrict__ A, const float* __restrict__ Bt,
    const float* __restrict__ bias, float* __restrict__ C,
    int M, int N, int K, int doBiasRelu)
{
    __shared__ __align__(16) unsigned short sAh[GBM * APITCH];
    __shared__ __align__(16) unsigned short sAl[GBM * APITCH];
    __shared__ __align__(16) unsigned short sBh[GBN * APITCH];
    __shared__ __align__(16) unsigned short sBl[GBN * APITCH];

    int tid  = threadIdx.x;
    int lane = tid & 31;
    int warp = tid >> 5;              // 0..7
    int warp_m = warp & 3;            // row base 32*warp_m
    int warp_n = warp >> 2;           // col base 64*warp_n
    int gid = lane >> 2;
    int tg  = lane & 3;

    int bm0 = blockIdx.x * GBM;
    int bn0 = blockIdx.y * GBN;

    uint32_t uAh = (uint32_t)__cvta_generic_to_shared(sAh);
    uint32_t uAl = (uint32_t)__cvta_generic_to_shared(sAl);
    uint32_t uBh = (uint32_t)__cvta_generic_to_shared(sBh);
    uint32_t uBl = (uint32_t)__cvta_generic_to_shared(sBl);

    // ldmatrix per-lane byte offsets
    int l = lane;
    uint32_t a_off = ((uint32_t)(warp_m * 32 + (l & 7) + ((l >> 3) & 1) * 8) * APITCH
                      + (l >> 4) * 8) * 2;
    uint32_t b_off = ((uint32_t)(warp_n * 64 + (l & 7) + (l >> 4) * 8) * APITCH
                      + ((l >> 3) & 1) * 8) * 2;

    float c[2][8][4];
    #pragma unroll
    for (int mt = 0; mt < 2; mt++)
        #pragma unroll
        for (int nt = 0; nt < 8; nt++)
            #pragma unroll
            for (int r = 0; r < 4; r++) c[mt][nt][r] = 0.f;

    for (int k0 = 0; k0 < K; k0 += GBK) {
        // A tile: 128 rows x 32 k (1024 float4)
        #pragma unroll
        for (int i = 0; i < 4; i++) {
            int idx = tid + i * 256;
            int r = idx >> 3, c4 = idx & 7;
            float4 v = make_float4(0.f, 0.f, 0.f, 0.f);
            if (bm0 + r < M)
                v = *(const float4*)&A[(size_t)(bm0 + r) * K + k0 + c4 * 4];
            uint32_t h0, l0, h1, l1;
            split2(v.x, v.y, h0, l0);
            split2(v.z, v.w, h1, l1);
            int off = (r * APITCH + c4 * 4) * 2;
            *(uint2*)((char*)sAh + off) = make_uint2(h0, h1);
            *(uint2*)((char*)sAl + off) = make_uint2(l0, l1);
        }
        // B tile from Bt[N][K]: rows always in-range (N=256)
        #pragma unroll
        for (int i = 0; i < 4; i++) {
            int idx = tid + i * 256;
            int r = idx >> 3, c4 = idx & 7;
            float4 v = *(const float4*)&Bt[(size_t)(bn0 + r) * K + k0 + c4 * 4];
            uint32_t h0, l0, h1, l1;
            split2(v.x, v.y, h0, l0);
            split2(v.z, v.w, h1, l1);
            int off = (r * APITCH + c4 * 4) * 2;
            *(uint2*)((char*)sBh + off) = make_uint2(h0, h1);
            *(uint2*)((char*)sBl + off) = make_uint2(l0, l1);
        }
        __syncthreads();

        #pragma unroll
        for (int ks = 0; ks < 2; ks++) {
            uint32_t kb2 = ks * 32;   // 16 halfwords -> bytes
            uint32_t ah[2][4], al[2][4];
            LDSM4(ah[0], uAh + a_off + kb2);
            LDSM4(ah[1], uAh + a_off + kb2 + 16 * APITCH * 2);
            LDSM4(al[0], uAl + a_off + kb2);
            LDSM4(al[1], uAl + a_off + kb2 + 16 * APITCH * 2);
            #pragma unroll
            for (int ng = 0; ng < 4; ng++) {
                uint32_t bh[4], bl[4];
                uint32_t boff = b_off + (uint32_t)ng * (16 * APITCH * 2) + kb2;
                LDSM4(bh, uBh + boff);
                LDSM4(bl, uBl + boff);
                int n0 = 2 * ng, n1 = 2 * ng + 1;
                // term hh
                MMA_BF16(c[0][n0], ah[0], bh[0], bh[1]);
                MMA_BF16(c[1][n0], ah[1], bh[0], bh[1]);
                MMA_BF16(c[0][n1], ah[0], bh[2], bh[3]);
                MMA_BF16(c[1][n1], ah[1], bh[2], bh[3]);
                // term lh
                MMA_BF16(c[0][n0], al[0], bh[0], bh[1]);
                MMA_BF16(c[1][n0], al[1], bh[0], bh[1]);
                MMA_BF16(c[0][n1], al[0], bh[2], bh[3]);
                MMA_BF16(c[1][n1], al[1], bh[2], bh[3]);
                // term hl
                MMA_BF16(c[0][n0], ah[0], bl[0], bl[1]);
                MMA_BF16(c[1][n0], ah[1], bl[0], bl[1]);
                MMA_BF16(c[0][n1], ah[0], bl[2], bl[3]);
                MMA_BF16(c[1][n1], ah[1], bl[2], bl[3]);
            }
        }
        __syncthreads();
    }

    // epilogue: c0/c1 at (row=gid, col=2tg,2tg+1), c2/c3 at row=gid+8
    #pragma unroll
    for (int mt = 0; mt < 2; mt++) {
        int rbase = bm0 + warp_m * 32 + mt * 16 + gid;
        #pragma unroll
        for (int nt = 0; nt < 8; nt++) {
            int col = bn0 + warp_n * 64 + nt * 8 + 2 * tg;
            float v0 = c[mt][nt][0], v1 = c[mt][nt][1];
            float v2 = c[mt][nt][2], v3 = c[mt][nt][3];
            if (doBiasRelu) {
                float bb0 = bias[col], bb1 = bias[col + 1];
                v0 = fmaxf(v0 + bb0, 0.f); v1 = fmaxf(v1 + bb1, 0.f);
                v2 = fmaxf(v2 + bb0, 0.f); v3 = fmaxf(v3 + bb1, 0.f);
            }
            if (rbase < M)     *(float2*)&C[(size_t)rbase * N + col]       = make_float2(v0, v1);
            if (rbase + 8 < M) *(float2*)&C[(size_t)(rbase + 8) * N + col] = make_float2(v2, v3);
        }
    }
}

// ---------------- pooling (seg_ids sorted) ----------------------------------
#define POOL_ROWS 512
__global__ void __launch_bounds__(256) pool_kernel(const int* __restrict__ seg) {
    __shared__ int segs[POOL_ROWS];
    int r0 = blockIdx.x * POOL_ROWS;
    int nr = min(POOL_ROWS, NN - r0);
    if (nr <= 0) return;
    for (int r = threadIdx.x; r < nr; r += blockDim.x) segs[r] = seg[r0 + r];
    __syncthreads();
    int col = threadIdx.x;  // 256 cols
    const float* h2 = (const float*)g_h2;
    float acc = 0.f;
    int cur = segs[0];
    for (int r = 0; r < nr; r++) {
        int s = segs[r];
        if (s != cur) { atomicAdd(&g_pool[cur * HID + col], acc); acc = 0.f; cur = s; }
        acc += h2[(size_t)(r0 + r) * HID + col];
    }
    atomicAdd(&g_pool[cur * HID + col], acc);
}

// ---------------- head: out = relu(g@Wd+bd) @ Wo + bo -----------------------
__global__ void __launch_bounds__(256) head_kernel(
    const float* __restrict__ Wd, const float* __restrict__ bd,
    const float* __restrict__ Wo, const float* __restrict__ bo,
    float* __restrict__ out)
{
    __shared__ float grow[HID];
    __shared__ float red[HID];
    int i = blockIdx.x, t = threadIdx.x;
    grow[t] = g_pool[i * HID + t];
    __syncthreads();
    float acc = bd[t];
    #pragma unroll 8
    for (int k = 0; k < HID; k++) acc += grow[k] * Wd[k * HID + t];
    acc = fmaxf(acc, 0.f);
    red[t] = acc * Wo[t];
    __syncthreads();
    for (int s = 128; s > 0; s >>= 1) {
        if (t < s) red[t] += red[t + s];
        __syncthreads();
    }
    if (t == 0) out[i] = red[0] + bo[0];
}

// ---------------- launch ----------------------------------------------------
extern "C" void kernel_launch(void* const* d_in, const int* in_sizes, int n_in,
                              void* d_out, int out_size)
{
    const float* x   = (const float*)d_in[0];
    const int*   esr = (const int*)  d_in[1];
    const int*   eds = (const int*)  d_in[2];
    const float* ew  = (const float*)d_in[3];
    const int*   seg = (const int*)  d_in[4];
    const float* W1  = (const float*)d_in[5];
    const float* b1  = (const float*)d_in[6];
    const float* W2  = (const float*)d_in[7];
    const float* b2  = (const float*)d_in[8];
    const float* Wd  = (const float*)d_in[9];
    const float* bd  = (const float*)d_in[10];
    const float* Wo  = (const float*)d_in[11];
    const float* bo  = (const float*)d_in[12];
    float* out = (float*)d_out;

    void *p_ax, *p_h1, *p_t2, *p_W1t, *p_W2t;
    cudaGetSymbolAddress(&p_ax, g_ax);
    cudaGetSymbolAddress(&p_h1, g_h1);
    cudaGetSymbolAddress(&p_t2, g_t2);
    cudaGetSymbolAddress(&p_W1t, g_W1t);
    cudaGetSymbolAddress(&p_W2t, g_W2t);

    // 1) zero counters + pool accumulator; transpose weights
    zero_kernel<<<(NN + 255) / 256, 256>>>();
    {
        dim3 g1(FIN / 32, HID / 32);
        transpose_kernel<<<g1, 256>>>(W1, (float*)p_W1t, FIN, HID);
        dim3 g2(HID / 32, HID / 32);
        transpose_kernel<<<g2, 256>>>(W2, (float*)p_W2t, HID, HID);
    }
    // 2) CSR build
    hist_kernel<<<(NE + 255) / 256, 256>>>(eds);
    scan_pre_kernel<<<NBLK, 256>>>();
    scan_mid_kernel<<<1, 256>>>();
    scan_post_kernel<<<NBLK, 256>>>();
    fill_kernel<<<(NE + 255) / 256, 256>>>(esr, eds, ew);
    // 3) spmm(x) -> ax  [N,128]
    spmm128_kernel<<<NN / 8, 256>>>((const float4*)x);
    // 4) h1 = relu(ax @ W1 + b1)
    {
        dim3 grid((NN + GBM - 1) / GBM, HID / GBN);
        gemm_bf16_ldsm_kernel<<<grid, 256>>>((const float*)p_ax, (const float*)p_W1t,
                                             b1, (float*)p_h1, NN, HID, FIN, 1);
    }
    // 5) t2 = h1 @ W2
    {
        dim3 grid((NN + GBM - 1) / GBM, HID / GBN);
        gemm_bf16_ldsm_kernel<<<grid, 256>>>((const float*)p_h1, (const float*)p_W2t,
                                             b1 /*unused*/, (float*)p_t2, NN, HID, HID, 0);
    }
    // 6) h2 = relu(spmm(t2) + b2)
    spmm256_kernel<<<NN / 8, 256>>>(b2);
    // 7) pool
    pool_kernel<<<(NN + POOL_ROWS - 1) / POOL_ROWS, 256>>>(seg);
    // 8) head
    head_kernel<<<NG, HID>>>(Wd, bd, Wo, bo, out);
}

// round 9
// speedup vs baseline: 1.1375x; 1.0239x over previous
#include <cuda_runtime.h>
#include <cuda_bf16.h>
#include <cuda_fp16.h>
#include <cstdint>

#define NN   50000
#define NE   800000
#define FIN  128
#define HID  256
#define NG   128
#define NBLK 196   // ceil(NN/256)

// ---------------- device scratch --------------------------------------------
__device__ __align__(16) __nv_bfloat16 g_axh[NN * FIN];   // split-bf16 spmm(x)
__device__ __align__(16) __nv_bfloat16 g_axl[NN * FIN];
__device__ __align__(16) __nv_bfloat16 g_h1h[NN * HID];   // split-bf16 h1
__device__ __align__(16) __nv_bfloat16 g_h1l[NN * HID];
__device__ __align__(16) __half       g_t2h[NN * HID];    // t2 = h1@W2, fp16
__device__ __align__(16) __half       g_x16[NN * FIN];    // x in fp16
__device__ float4 g_h2[NN * HID / 4];                     // relu(spmm(t2)+b2)
__device__ __align__(16) __nv_bfloat16 g_W1th[HID * FIN]; // W1^T split-bf16
__device__ __align__(16) __nv_bfloat16 g_W1tl[HID * FIN];
__device__ __align__(16) __nv_bfloat16 g_W2th[HID * HID];
__device__ __align__(16) __nv_bfloat16 g_W2tl[HID * HID];
__device__ int    g_deg[NN];
__device__ int    g_rp[NN + 1];
__device__ int    g_cursor[NN];
__device__ int    g_srcs[NE];
__device__ float  g_ws[NE];
__device__ float  g_pool[NG * HID];
__device__ int    g_bsum[256];
__device__ int    g_bpre[256];

// ---------------- helpers ---------------------------------------------------
__device__ __forceinline__ uint32_t pack2(__nv_bfloat16 lo, __nv_bfloat16 hi) {
    __nv_bfloat162 t = __halves2bfloat162(lo, hi);  // .x -> low 16 bits
    return *(uint32_t*)&t;
}
__device__ __forceinline__ void splitf(float a, __nv_bfloat16& h, __nv_bfloat16& l) {
    h = __float2bfloat16_rn(a);
    l = __float2bfloat16_rn(a - __bfloat162float(h));
}
__device__ __forceinline__ void cp16(uint32_t dst, const void* src, bool p) {
    asm volatile("cp.async.cg.shared.global [%0], [%1], 16, %2;"
                 :: "r"(dst), "l"(src), "r"(p ? 16 : 0));
}

// ---------------- CSR build -------------------------------------------------
__global__ void zero_kernel() {
    int i = blockIdx.x * blockDim.x + threadIdx.x;
    if (i < NN) g_deg[i] = 0;
    if (i < NG * HID) g_pool[i] = 0.0f;
}

__global__ void hist_kernel(const int* __restrict__ dst) {
    int e = blockIdx.x * blockDim.x + threadIdx.x;
    if (e < NE) atomicAdd(&g_deg[dst[e]], 1);
}

__global__ void __launch_bounds__(256) scan_pre_kernel() {
    __shared__ int s[256];
    int i = blockIdx.x * 256 + threadIdx.x;
    int v = (i < NN) ? g_deg[i] : 0;
    s[threadIdx.x] = v;
    __syncthreads();
    for (int off = 128; off > 0; off >>= 1) {
        if (threadIdx.x < off) s[threadIdx.x] += s[threadIdx.x + off];
        __syncthreads();
    }
    if (threadIdx.x == 0) g_bsum[blockIdx.x] = s[0];
}

__global__ void __launch_bounds__(256) scan_mid_kernel() {
    __shared__ int s[256];
    int t = threadIdx.x;
    int v = (t < NBLK) ? g_bsum[t] : 0;
    s[t] = v;
    __syncthreads();
    for (int off = 1; off < 256; off <<= 1) {
        int add = (t >= off) ? s[t - off] : 0;
        __syncthreads();
        s[t] += add;
        __syncthreads();
    }
    g_bpre[t] = s[t] - v;
    if (t == 255) g_rp[NN] = s[255];
}

__global__ void __launch_bounds__(256) scan_post_kernel() {
    __shared__ int wsum[8];
    int t = threadIdx.x, lane = t & 31, w = t >> 5;
    int i = blockIdx.x * 256 + t;
    int v = (i < NN) ? g_deg[i] : 0;
    int incl = v;
    #pragma unroll
    for (int o = 1; o < 32; o <<= 1) {
        int x = __shfl_up_sync(0xffffffffu, incl, o);
        if (lane >= o) incl += x;
    }
    if (lane == 31) wsum[w] = incl;
    __syncthreads();
    if (w == 0 && lane < 8) {
        int x = wsum[lane];
        #pragma unroll
        for (int o = 1; o < 8; o <<= 1) {
            int y = __shfl_up_sync(0xffu, x, o);
            if (lane >= o) x += y;
        }
        wsum[lane] = x;
    }
    __syncthreads();
    int base = g_bpre[blockIdx.x] + ((w > 0) ? wsum[w - 1] : 0);
    int excl = base + incl - v;
    if (i < NN) { g_rp[i] = excl; g_cursor[i] = excl; }
}

__global__ void fill_kernel(const int* __restrict__ src, const int* __restrict__ dst,
                            const float* __restrict__ ew) {
    int e = blockIdx.x * blockDim.x + threadIdx.x;
    if (e < NE) {
        int p = atomicAdd(&g_cursor[dst[e]], 1);
        g_srcs[p] = src[e];
        g_ws[p]   = ew[e];
    }
}

// ---------------- x -> fp16 -------------------------------------------------
__global__ void __launch_bounds__(256) x2h_kernel(const float2* __restrict__ x2) {
    int i = blockIdx.x * blockDim.x + threadIdx.x;
    if (i < NN * FIN / 2) {
        float2 v = x2[i];
        ((__half2*)g_x16)[i] = __floats2half2_rn(v.x, v.y);
    }
}

// ---------------- weight transpose + split: W[K,N] -> (h,l)[N,K] ------------
__global__ void __launch_bounds__(256) transpose_split_kernel(
    const float* __restrict__ src, __nv_bfloat16* __restrict__ dh,
    __nv_bfloat16* __restrict__ dl, int K, int N)
{
    __shared__ float tile[32][33];
    int kb = blockIdx.x * 32, nb = blockIdx.y * 32;
    int tx = threadIdx.x & 31, ty = threadIdx.x >> 5;   // 32 x 8
    #pragma unroll
    for (int j = 0; j < 4; j++)
        tile[ty + 8 * j][tx] = src[(size_t)(kb + ty + 8 * j) * N + nb + tx];
    __syncthreads();
    #pragma unroll
    for (int j = 0; j < 4; j++) {
        float v = tile[tx][ty + 8 * j];
        __nv_bfloat16 h, l;
        splitf(v, h, l);
        size_t o = (size_t)(nb + ty + 8 * j) * K + kb + tx;
        dh[o] = h; dl[o] = l;
    }
}

// ---------------- SPMM 1: warp per dst node, fp16 gather, split-bf16 out ----
__global__ void __launch_bounds__(256) spmm128_kernel() {
    int warp = (blockIdx.x * blockDim.x + threadIdx.x) >> 5;
    int lane = threadIdx.x & 31;
    if (warp >= NN) return;
    int e0 = g_rp[warp], e1 = g_rp[warp + 1];
    float4 acc = make_float4(0.f, 0.f, 0.f, 0.f);
    for (int e = e0; e < e1; e++) {
        int   s = g_srcs[e];
        float w = g_ws[e];
        uint2 u = __ldg((const uint2*)(g_x16 + (size_t)s * FIN + lane * 4));
        float2 f0 = __half22float2(*(__half2*)&u.x);
        float2 f1 = __half22float2(*(__half2*)&u.y);
        acc.x += w * f0.x; acc.y += w * f0.y;
        acc.z += w * f1.x; acc.w += w * f1.y;
    }
    __nv_bfloat16 h0, l0, h1, l1, h2, l2, h3, l3;
    splitf(acc.x, h0, l0); splitf(acc.y, h1, l1);
    splitf(acc.z, h2, l2); splitf(acc.w, h3, l3);
    size_t o = (size_t)warp * FIN + lane * 4;
    *(uint2*)(g_axh + o) = make_uint2(pack2(h0, h1), pack2(h2, h3));
    *(uint2*)(g_axl + o) = make_uint2(pack2(l0, l1), pack2(l2, l3));
}

// ---------------- SPMM 2: fp16 gather of t2, +bias, relu, fp32 out ----------
__global__ void __launch_bounds__(256) spmm256_kernel(const float* __restrict__ b2) {
    int warp = (blockIdx.x * blockDim.x + threadIdx.x) >> 5;
    int lane = threadIdx.x & 31;
    if (warp >= NN) return;
    int e0 = g_rp[warp], e1 = g_rp[warp + 1];
    float a[8];
    #pragma unroll
    for (int j = 0; j < 8; j++) a[j] = 0.f;
    for (int e = e0; e < e1; e++) {
        int   s = g_srcs[e];
        float w = g_ws[e];
        uint4 u = __ldg((const uint4*)(g_t2h + (size_t)s * HID + lane * 8));
        float2 f0 = __half22float2(*(__half2*)&u.x);
        float2 f1 = __half22float2(*(__half2*)&u.y);
        float2 f2 = __half22float2(*(__half2*)&u.z);
        float2 f3 = __half22float2(*(__half2*)&u.w);
        a[0] += w * f0.x; a[1] += w * f0.y;
        a[2] += w * f1.x; a[3] += w * f1.y;
        a[4] += w * f2.x; a[5] += w * f2.y;
        a[6] += w * f3.x; a[7] += w * f3.y;
    }
    const float4* b4 = (const float4*)b2;
    float4 c0 = __ldg(&b4[lane * 2]);
    float4 c1 = __ldg(&b4[lane * 2 + 1]);
    float4 o0, o1;
    o0.x = fmaxf(a[0] + c0.x, 0.f); o0.y = fmaxf(a[1] + c0.y, 0.f);
    o0.z = fmaxf(a[2] + c0.z, 0.f); o0.w = fmaxf(a[3] + c0.w, 0.f);
    o1.x = fmaxf(a[4] + c1.x, 0.f); o1.y = fmaxf(a[5] + c1.y, 0.f);
    o1.z = fmaxf(a[6] + c1.z, 0.f); o1.w = fmaxf(a[7] + c1.w, 0.f);
    g_h2[warp * (HID / 4) + lane * 2]     = o0;
    g_h2[warp * (HID / 4) + lane * 2 + 1] = o1;
}

// ---------------- pipelined split-bf16 tensor-core GEMM ---------------------
// C = A[M,K] @ B^T[N,K] (+bias, relu); A,B pre-split bf16 (h,l) arrays.
// 3-term: C = Ah*Bh + Al*Bh + Ah*Bl. cp.async 2-stage double buffer.
// smem tiles [row][k] bf16, pitch 40 hw (80B): ldmatrix conflict-free.
#define GBM 128
#define GBN 128
#define GBK 32
#define APITCH 40
#define STG_HW (GBM * APITCH)   // 5120 halfwords per tile-stage
#define GEMM_SMEM (8 * STG_HW * 2)  // bytes

#define LDSM4(R, addr)                                                         \
    asm volatile("ldmatrix.sync.aligned.m8n8.x4.shared.b16 {%0,%1,%2,%3}, [%4];" \
        : "=r"(R[0]), "=r"(R[1]), "=r"(R[2]), "=r"(R[3]) : "r"(addr))

#define MMA_BF16(C, A, B0, B1)                                                 \
    asm volatile(                                                              \
        "mma.sync.aligned.m16n8k16.row.col.f32.bf16.bf16.f32 "                 \
        "{%0,%1,%2,%3}, {%4,%5,%6,%7}, {%8,%9}, {%0,%1,%2,%3};"                \
        : "+f"(C[0]), "+f"(C[1]), "+f"(C[2]), "+f"(C[3])                       \
        : "r"(A[0]), "r"(A[1]), "r"(A[2]), "r"(A[3]), "r"(B0), "r"(B1))

__global__ void __launch_bounds__(256, 2) gemm_pipe_kernel(
    const __nv_bfloat16* __restrict__ Ah, const __nv_bfloat16* __restrict__ Al,
    const __nv_bfloat16* __restrict__ Bh, const __nv_bfloat16* __restrict__ Bl,
    const float* __restrict__ bias,
    __nv_bfloat16* __restrict__ Oh, __nv_bfloat16* __restrict__ Ol,
    __half* __restrict__ O16,
    int M, int N, int K, int mode)   // mode 1: bias+relu, split-bf16 out; 0: fp16 out
{
    extern __shared__ __align__(16) unsigned short smem[];
    uint32_t ubase = (uint32_t)__cvta_generic_to_shared(smem);

    int tid  = threadIdx.x;
    int lane = tid & 31;
    int warp = tid >> 5;
    int warp_m = warp & 3;
    int warp_n = warp >> 2;
    int gid = lane >> 2;
    int tg  = lane & 3;

    int bm0 = blockIdx.x * GBM;
    int bn0 = blockIdx.y * GBN;

    // ldmatrix per-lane byte offsets (within a tile-stage)
    int l = lane;
    uint32_t a_off = ((uint32_t)(warp_m * 32 + (l & 7) + ((l >> 3) & 1) * 8) * APITCH
                      + (l >> 4) * 8) * 2;
    uint32_t b_off = ((uint32_t)(warp_n * 64 + (l & 7) + (l >> 4) * 8) * APITCH
                      + ((l >> 3) & 1) * 8) * 2;

    float c[2][8][4];
    #pragma unroll
    for (int mt = 0; mt < 2; mt++)
        #pragma unroll
        for (int nt = 0; nt < 8; nt++)
            #pragma unroll
            for (int r = 0; r < 4; r++) c[mt][nt][r] = 0.f;

    // prefetch one stage: 8 cp.async of 16B per thread
    auto prefetch = [&](int stage, int k0) {
        #pragma unroll
        for (int i = 0; i < 4; i++) {
            int idx = tid + i * 256;                 // 0..1023
            int arr = idx >> 9, rc = idx & 511;
            int row = rc >> 2, cc = rc & 3;
            const __nv_bfloat16* g = (arr ? Al : Ah)
                + (size_t)(bm0 + row) * K + k0 + cc * 8;
            uint32_t d = ubase + (uint32_t)((arr ? 2 * STG_HW : 0)
                + stage * STG_HW + row * APITCH + cc * 8) * 2;
            cp16(d, g, bm0 + row < M);
        }
        #pragma unroll
        for (int i = 0; i < 4; i++) {
            int idx = tid + i * 256;
            int arr = idx >> 9, rc = idx & 511;
            int row = rc >> 2, cc = rc & 3;
            const __nv_bfloat16* g = (arr ? Bl : Bh)
                + (size_t)(bn0 + row) * K + k0 + cc * 8;
            uint32_t d = ubase + (uint32_t)((arr ? 6 * STG_HW : 4 * STG_HW)
                + stage * STG_HW + row * APITCH + cc * 8) * 2;
            cp16(d, g, true);
        }
        asm volatile("cp.async.commit_group;");
    };

    int nk = K / GBK;
    prefetch(0, 0);

    for (int it = 0; it < nk; it++) {
        int cur = it & 1;
        if (it + 1 < nk) prefetch((it + 1) & 1, (it + 1) * GBK);
        if (it + 1 < nk) { asm volatile("cp.async.wait_group 1;"); }
        else             { asm volatile("cp.async.wait_group 0;"); }
        __syncthreads();

        uint32_t uAh = ubase + (uint32_t)(cur * STG_HW) * 2;
        uint32_t uAl = ubase + (uint32_t)(2 * STG_HW + cur * STG_HW) * 2;
        uint32_t uBh = ubase + (uint32_t)(4 * STG_HW + cur * STG_HW) * 2;
        uint32_t uBl = ubase + (uint32_t)(6 * STG_HW + cur * STG_HW) * 2;

        #pragma unroll
        for (int ks = 0; ks < 2; ks++) {
            uint32_t kb2 = ks * 32;
            uint32_t ah[2][4], al[2][4];
            LDSM4(ah[0], uAh + a_off + kb2);
            LDSM4(ah[1], uAh + a_off + kb2 + 16 * APITCH * 2);
            LDSM4(al[0], uAl + a_off + kb2);
            LDSM4(al[1], uAl + a_off + kb2 + 16 * APITCH * 2);
            #pragma unroll
            for (int ng = 0; ng < 4; ng++) {
                uint32_t bh[4], bl[4];
                uint32_t boff = b_off + (uint32_t)ng * (16 * APITCH * 2) + kb2;
                LDSM4(bh, uBh + boff);
                LDSM4(bl, uBl + boff);
                int n0 = 2 * ng, n1 = 2 * ng + 1;
                MMA_BF16(c[0][n0], ah[0], bh[0], bh[1]);
                MMA_BF16(c[1][n0], ah[1], bh[0], bh[1]);
                MMA_BF16(c[0][n1], ah[0], bh[2], bh[3]);
                MMA_BF16(c[1][n1], ah[1], bh[2], bh[3]);
                MMA_BF16(c[0][n0], al[0], bh[0], bh[1]);
                MMA_BF16(c[1][n0], al[1], bh[0], bh[1]);
                MMA_BF16(c[0][n1], al[0], bh[2], bh[3]);
                MMA_BF16(c[1][n1], al[1], bh[2], bh[3]);
                MMA_BF16(c[0][n0], ah[0], bl[0], bl[1]);
                MMA_BF16(c[1][n0], ah[1], bl[0], bl[1]);
                MMA_BF16(c[0][n1], ah[0], bl[2], bl[3]);
                MMA_BF16(c[1][n1], ah[1], bl[2], bl[3]);
            }
        }
        __syncthreads();
    }

    // epilogue
    #pragma unroll
    for (int mt = 0; mt < 2; mt++) {
        int rbase = bm0 + warp_m * 32 + mt * 16 + gid;
        #pragma unroll
        for (int nt = 0; nt < 8; nt++) {
            int col = bn0 + warp_n * 64 + nt * 8 + 2 * tg;
            float v0 = c[mt][nt][0], v1 = c[mt][nt][1];
            float v2 = c[mt][nt][2], v3 = c[mt][nt][3];
            if (mode) {
                float bb0 = bias[col], bb1 = bias[col + 1];
                v0 = fmaxf(v0 + bb0, 0.f); v1 = fmaxf(v1 + bb1, 0.f);
                v2 = fmaxf(v2 + bb0, 0.f); v3 = fmaxf(v3 + bb1, 0.f);
                __nv_bfloat16 h0, l0, h1, l1;
                if (rbase < M) {
                    splitf(v0, h0, l0); splitf(v1, h1, l1);
                    *(uint32_t*)&Oh[(size_t)rbase * N + col] = pack2(h0, h1);
                    *(uint32_t*)&Ol[(size_t)rbase * N + col] = pack2(l0, l1);
                }
                if (rbase + 8 < M) {
                    splitf(v2, h0, l0); splitf(v3, h1, l1);
                    *(uint32_t*)&Oh[(size_t)(rbase + 8) * N + col] = pack2(h0, h1);
                    *(uint32_t*)&Ol[(size_t)(rbase + 8) * N + col] = pack2(l0, l1);
                }
            } else {
                if (rbase < M)
                    *(__half2*)&O16[(size_t)rbase * N + col] = __floats2half2_rn(v0, v1);
                if (rbase + 8 < M)
                    *(__half2*)&O16[(size_t)(rbase + 8) * N + col] = __floats2half2_rn(v2, v3);
            }
        }
    }
}

// ---------------- pooling (seg_ids sorted) ----------------------------------
#define POOL_ROWS 512
__global__ void __launch_bounds__(256) pool_kernel(const int* __restrict__ seg) {
    __shared__ int segs[POOL_ROWS];
    int r0 = blockIdx.x * POOL_ROWS;
    int nr = min(POOL_ROWS, NN - r0);
    if (nr <= 0) return;
    for (int r = threadIdx.x; r < nr; r += blockDim.x) segs[r] = seg[r0 + r];
    __syncthreads();
    int col = threadIdx.x;
    const float* h2 = (const float*)g_h2;
    float acc = 0.f;
    int cur = segs[0];
    for (int r = 0; r < nr; r++) {
        int s = segs[r];
        if (s != cur) { atomicAdd(&g_pool[cur * HID + col], acc); acc = 0.f; cur = s; }
        acc += h2[(size_t)(r0 + r) * HID + col];
    }
    atomicAdd(&g_pool[cur * HID + col], acc);
}

// ---------------- head: out = relu(g@Wd+bd) @ Wo + bo -----------------------
__global__ void __launch_bounds__(256) head_kernel(
    const float* __restrict__ Wd, const float* __restrict__ bd,
    const float* __restrict__ Wo, const float* __restrict__ bo,
    float* __restrict__ out)
{
    __shared__ float grow[HID];
    __shared__ float red[HID];
    int i = blockIdx.x, t = threadIdx.x;
    grow[t] = g_pool[i * HID + t];
    __syncthreads();
    float acc = bd[t];
    #pragma unroll 8
    for (int k = 0; k < HID; k++) acc += grow[k] * Wd[k * HID + t];
    acc = fmaxf(acc, 0.f);
    red[t] = acc * Wo[t];
    __syncthreads();
    for (int s = 128; s > 0; s >>= 1) {
        if (t < s) red[t] += red[t + s];
        __syncthreads();
    }
    if (t == 0) out[i] = red[0] + bo[0];
}

// ---------------- launch ----------------------------------------------------
extern "C" void kernel_launch(void* const* d_in, const int* in_sizes, int n_in,
                              void* d_out, int out_size)
{
    const float* x   = (const float*)d_in[0];
    const int*   esr = (const int*)  d_in[1];
    const int*   eds = (const int*)  d_in[2];
    const float* ew  = (const float*)d_in[3];
    const int*   seg = (const int*)  d_in[4];
    const float* W1  = (const float*)d_in[5];
    const float* b1  = (const float*)d_in[6];
    const float* W2  = (const float*)d_in[7];
    const float* b2  = (const float*)d_in[8];
    const float* Wd  = (const float*)d_in[9];
    const float* bd  = (const float*)d_in[10];
    const float* Wo  = (const float*)d_in[11];
    const float* bo  = (const float*)d_in[12];
    float* out = (float*)d_out;

    static int smem_set = 0;
    if (!smem_set) {
        cudaFuncSetAttribute(gemm_pipe_kernel,
                             cudaFuncAttributeMaxDynamicSharedMemorySize, GEMM_SMEM);
        smem_set = 1;
    }

    void *p_axh, *p_axl, *p_h1h, *p_h1l, *p_t2h;
    void *p_W1th, *p_W1tl, *p_W2th, *p_W2tl;
    cudaGetSymbolAddress(&p_axh, g_axh);
    cudaGetSymbolAddress(&p_axl, g_axl);
    cudaGetSymbolAddress(&p_h1h, g_h1h);
    cudaGetSymbolAddress(&p_h1l, g_h1l);
    cudaGetSymbolAddress(&p_t2h, g_t2h);
    cudaGetSymbolAddress(&p_W1th, g_W1th);
    cudaGetSymbolAddress(&p_W1tl, g_W1tl);
    cudaGetSymbolAddress(&p_W2th, g_W2th);
    cudaGetSymbolAddress(&p_W2tl, g_W2tl);

    // 1) zero; x->fp16; weight transpose+split
    zero_kernel<<<(NN + 255) / 256, 256>>>();
    x2h_kernel<<<(NN * FIN / 2 + 255) / 256, 256>>>((const float2*)x);
    {
        dim3 g1(FIN / 32, HID / 32);
        transpose_split_kernel<<<g1, 256>>>(W1, (__nv_bfloat16*)p_W1th,
                                            (__nv_bfloat16*)p_W1tl, FIN, HID);
        dim3 g2(HID / 32, HID / 32);
        transpose_split_kernel<<<g2, 256>>>(W2, (__nv_bfloat16*)p_W2th,
                                            (__nv_bfloat16*)p_W2tl, HID, HID);
    }
    // 2) CSR build
    hist_kernel<<<(NE + 255) / 256, 256>>>(eds);
    scan_pre_kernel<<<NBLK, 256>>>();
    scan_mid_kernel<<<1, 256>>>();
    scan_post_kernel<<<NBLK, 256>>>();
    fill_kernel<<<(NE + 255) / 256, 256>>>(esr, eds, ew);
    // 3) spmm(x) -> (axh, axl)
    spmm128_kernel<<<NN / 8, 256>>>();
    // 4) h1 = relu(ax @ W1 + b1) -> (h1h, h1l)
    {
        dim3 grid((NN + GBM - 1) / GBM, HID / GBN);
        gemm_pipe_kernel<<<grid, 256, GEMM_SMEM>>>(
            (const __nv_bfloat16*)p_axh, (const __nv_bfloat16*)p_axl,
            (const __nv_bfloat16*)p_W1th, (const __nv_bfloat16*)p_W1tl,
            b1, (__nv_bfloat16*)p_h1h, (__nv_bfloat16*)p_h1l, nullptr,
            NN, HID, FIN, 1);
    }
    // 5) t2 = h1 @ W2 -> fp16
    {
        dim3 grid((NN + GBM - 1) / GBM, HID / GBN);
        gemm_pipe_kernel<<<grid, 256, GEMM_SMEM>>>(
            (const __nv_bfloat16*)p_h1h, (const __nv_bfloat16*)p_h1l,
            (const __nv_bfloat16*)p_W2th, (const __nv_bfloat16*)p_W2tl,
            b1 /*unused*/, nullptr, nullptr, (__half*)p_t2h,
            NN, HID, HID, 0);
    }
    // 6) h2 = relu(spmm(t2) + b2)
    spmm256_kernel<<<NN / 8, 256>>>(b2);
    // 7) pool
    pool_kernel<<<(NN + POOL_ROWS - 1) / POOL_ROWS, 256>>>(seg);
    // 8) head
    head_kernel<<<NG, HID>>>(Wd, bd, Wo, bo, out);
}